// round 14
// baseline (speedup 1.0000x reference)
#include <cuda_runtime.h>

#define Bsz 200
#define Tsz 250
#define Fsz 14
#define Hsz 256
#define G4  1024
#define Dsz 164
#define Csz 8
#define NCOLT 16
#define NROWT 9
#define RPT   24
#define ZS_LD 25
#define P2M   128
#define NTHR  384

__device__ float g_xz2[Tsz * Bsz * G4];
__device__ float g_seq[Tsz * Bsz * Hsz];
__device__ float g_h1a[Bsz * Hsz];
__device__ float g_h1b[Bsz * Hsz];
__device__ float g_h2a[Bsz * Hsz];
__device__ float g_h2b[Bsz * Hsz];
__device__ unsigned g_scnt[2][NROWT][Tsz];   // per-step arrival counters

__device__ __forceinline__ void ffma2(unsigned long long& d, unsigned long long a, unsigned long long b) {
    asm("fma.rn.f32x2 %0, %1, %2, %0;" : "+l"(d) : "l"(a), "l"(b));
}
__device__ __forceinline__ void unpack2(unsigned long long v, float& lo, float& hi) {
    unsigned int l, h;
    asm("mov.b64 {%0, %1}, %2;" : "=r"(l), "=r"(h) : "l"(v));
    lo = __uint_as_float(l); hi = __uint_as_float(h);
}
__device__ __forceinline__ unsigned ld_acquire(const unsigned* p) {
    unsigned v;
    asm volatile("ld.acquire.gpu.u32 %0, [%1];" : "=r"(v) : "l"(p) : "memory");
    return v;
}
// ACCURATE activations — the recurrence compounds error over 250 steps.
// Fast __expf tanh measured at rel_err 1.2e-3 (FAIL); these give 6.9e-8.
__device__ __forceinline__ float sigmoidf_(float x) {
    return 1.0f / (1.0f + __expf(-x));
}
__device__ __forceinline__ float tanh_acc(float x) { return tanhf(x); }

__global__ void zero_state() {
    int i = blockIdx.x * blockDim.x + threadIdx.x;
    if (i < 2 * NROWT * Tsz) ((unsigned*)g_scnt)[i] = 0u;
}

// persistent LSTM layer: grid (16,9)=144 CTAs, 384 thr, all 250 steps inside.
// CTA tile 24 rows x 16 h-cols (64 gate cols).
// warp w: rowthr = w%3 (8 rows), kg = w/3 (64 k). lane owns gate-cols c, c+32.
// Everything from poll to zs-write is warp-local (no block sync before GEMM).
__global__ __launch_bounds__(NTHR, 1) void lstm_layer(
    int layer, const float* __restrict__ U,
    const float* __restrict__ W1, const float* __restrict__ b1,
    const float* __restrict__ inputs)
{
    extern __shared__ float smem[];
    float* ust = smem;                    // [64][256] U strip, rotation-swizzled
    float* hst = ust + 64 * 256;          // [24][256] h tile, row-major
    float* zs  = hst + RPT * 256;         // [4][64][ZS_LD] partials per k-quarter
    float* w1s = zs + 4 * 64 * ZS_LD;     // [14][64]
    float* b1s = w1s + Fsz * 64;          // [64]
    float* xin = b1s + 64;                // [24][16]
    __shared__ float csh[RPT * 16];       // cell state, CTA-private

    const int tid   = threadIdx.x;
    const int jbase = blockIdx.x * 16;
    const int grp   = blockIdx.y;
    const int rbase = grp * RPT;

    float* ha = layer ? g_h2a : g_h1a;
    float* hb = layer ? g_h2b : g_h1b;

    // ---- one-time staging ----
    for (int idx = tid; idx < 64 * 256; idx += NTHR) {
        int k = idx >> 6, c = idx & 63;
        float u = __ldg(U + k * G4 + ((c >> 4) << 8) + jbase + (c & 15));
        ust[c * 256 + ((((k >> 2) + c) & 63) << 2) + (k & 3)] = u;
    }
    if (layer == 0) {
        for (int idx = tid; idx < Fsz * 64; idx += NTHR) {
            int f = idx >> 6, c = idx & 63;
            w1s[idx] = W1[f * G4 + ((c >> 4) << 8) + jbase + (c & 15)];
        }
        if (tid < 64) b1s[tid] = b1[((tid >> 4) << 8) + jbase + (tid & 15)];
    }
    csh[tid] = 0.f;
    __syncthreads();

    const int w      = tid >> 5;
    const int lane   = tid & 31;
    const int c      = lane;              // owns gate-cols c and c+32
    const int rowthr = w % 3;
    const int kg     = w / 3;
    const int r0     = rowthr * 8;
    const int kbase  = kg * 64;
    const float* u0 = ust + c * 256;
    const float* u1 = ust + (c + 32) * 256;
    const int o0 = (kbase >> 2) + c;
    const int o1 = (kbase >> 2) + c + 32;
    const float* hlp = hst + r0 * 256 + kbase;
    float* zq = zs + kg * (64 * ZS_LD);
    const int gj = tid & 15, gr = tid >> 4;   // gate-cell mapping (all 384)

    for (int t = 0; t < Tsz; ++t) {
        const float* hin  = (t & 1) ? hb : ha;
        float*       hout = (t & 1) ? ha : hb;

        // ---- prefetch (regs, independent of h(t)) ----
        float xzv[4];
        if (layer) {
            int row = rbase + gr;
            const float* xzt = g_xz2 + ((size_t)t * Bsz + row) * G4;
            bool ok = row < Bsz;
            #pragma unroll
            for (int g = 0; g < 4; ++g)
                xzv[g] = ok ? __ldg(xzt + g * 256 + jbase + gj) : 0.f;
        }
        float xpin[4];
        if (layer == 0 && kg == 0) {
            #pragma unroll
            for (int i = 0; i < 4; ++i) {
                int idx = lane + i * 32;            // 0..127: 8 rows x 16 slots
                int rr = r0 + (idx >> 4), f = idx & 15;
                int row = rbase + rr;
                xpin[i] = (row < Bsz && f < Fsz)
                        ? __ldg(inputs + ((size_t)row * Tsz + t) * Fsz + f) : 0.f;
            }
        }

        // ---- warp-autonomous wait for step t-1 of this row group ----
        if (t > 0) {
            if (lane == 0) {
                const unsigned* sc = &g_scnt[layer][grp][t - 1];
                while (ld_acquire(sc) != (unsigned)NCOLT) { }
            }
            __syncwarp();
        }

        // ---- warp-local h staging: this warp's 8 rows x its 64-k quarter ----
        float4* hst4 = (float4*)hst;
        if (t == 0) {
            #pragma unroll
            for (int i = 0; i < 4; ++i) {
                int idx = lane + i * 32;            // 0..127: 8 rows x 16 float4
                int rr = idx >> 4, k4 = idx & 15;
                hst4[(r0 + rr) * 64 + (kbase >> 2) + k4] = make_float4(0.f, 0.f, 0.f, 0.f);
            }
        } else {
            const float4* hin4 = (const float4*)hin;
            float4 tf[4];
            #pragma unroll
            for (int i = 0; i < 4; ++i) {
                int idx = lane + i * 32;
                int rr = idx >> 4, k4 = idx & 15;
                int row = rbase + r0 + rr;
                tf[i] = (row < Bsz) ? __ldcg(hin4 + (size_t)row * 64 + (kbase >> 2) + k4)
                                    : make_float4(0.f, 0.f, 0.f, 0.f);
            }
            #pragma unroll
            for (int i = 0; i < 4; ++i) {
                int idx = lane + i * 32;
                int rr = idx >> 4, k4 = idx & 15;
                hst4[(r0 + rr) * 64 + (kbase >> 2) + k4] = tf[i];
            }
        }
        if (layer == 0 && kg == 0) {
            #pragma unroll
            for (int i = 0; i < 4; ++i)
                xin[r0 * 16 + lane + i * 32] = xpin[i];
        }
        __syncwarp();

        // ---- recurrent GEMM (2 cols x 8 rows, this k-quarter) ----
        unsigned long long A0[8], A1[8];
        #pragma unroll
        for (int i = 0; i < 8; ++i) { A0[i] = 0ull; A1[i] = 0ull; }
        #pragma unroll 8
        for (int k = 0; k < 64; k += 4) {
            int i4 = k >> 2;
            ulonglong2 uva = *reinterpret_cast<const ulonglong2*>(u0 + (((o0 + i4) & 63) << 2));
            ulonglong2 uvb = *reinterpret_cast<const ulonglong2*>(u1 + (((o1 + i4) & 63) << 2));
            #pragma unroll
            for (int i = 0; i < 8; ++i) {
                ulonglong2 hv = *reinterpret_cast<const ulonglong2*>(hlp + i * 256 + k);
                ffma2(A0[i], hv.x, uva.x); ffma2(A0[i], hv.y, uva.y);
                ffma2(A1[i], hv.x, uvb.x); ffma2(A1[i], hv.y, uvb.y);
            }
        }
        float zA[8], zB[8];
        #pragma unroll
        for (int i = 0; i < 8; ++i) {
            float lo, hi;
            unpack2(A0[i], lo, hi); zA[i] = lo + hi;
            unpack2(A1[i], lo, hi); zB[i] = lo + hi;
        }

        // layer-0 input projection folded in by kg==0 warps
        if (layer == 0 && kg == 0) {
            float wA[Fsz], wB[Fsz];
            #pragma unroll
            for (int f = 0; f < Fsz; ++f) {
                wA[f] = w1s[f * 64 + c];
                wB[f] = w1s[f * 64 + c + 32];
            }
            float bA = b1s[c], bB = b1s[c + 32];
            #pragma unroll
            for (int i = 0; i < 8; ++i) {
                float sA = bA, sB = bB;
                #pragma unroll
                for (int f = 0; f < Fsz; ++f) {
                    float xv = xin[(r0 + i) * 16 + f];
                    sA += xv * wA[f];
                    sB += xv * wB[f];
                }
                zA[i] += sA;
                zB[i] += sB;
            }
        }
        #pragma unroll
        for (int i = 0; i < 8; ++i) {
            zq[c * ZS_LD + r0 + i]        = zA[i];
            zq[(c + 32) * ZS_LD + r0 + i] = zB[i];
        }
        __syncthreads();

        // ---- gate combine: 384 cells, 1 per thread; sum 4 k-quarter partials ----
        float hn_keep = 0.f;
        int   gidx_keep = -1;
        {
            int row = rbase + gr;
            if (row < Bsz) {
                float zg4[4];
                #pragma unroll
                for (int g = 0; g < 4; ++g) {
                    float s = 0.f;
                    #pragma unroll
                    for (int q = 0; q < 4; ++q)
                        s += zs[q * (64 * ZS_LD) + (g * 16 + gj) * ZS_LD + gr];
                    if (layer) s += xzv[g];
                    zg4[g] = s;
                }
                float ig = sigmoidf_(zg4[0]), fg = sigmoidf_(zg4[1]);
                float gv = tanh_acc(zg4[2]), og = sigmoidf_(zg4[3]);
                float cn = fg * csh[tid] + ig * gv;
                csh[tid] = cn;
                float hn = og * tanh_acc(cn);
                int gidx = row * Hsz + jbase + gj;
                hout[gidx] = hn;                    // critical store first
                hn_keep = hn; gidx_keep = gidx;
            }
        }

        // ---- release; g_seq store off critical path ----
        __syncthreads();
        if (tid == 0) {
            __threadfence();
            atomicAdd(&g_scnt[layer][grp][t], 1u);
        }
        if (layer == 0 && gidx_keep >= 0)
            g_seq[(size_t)t * Bsz * Hsz + gidx_keep] = hn_keep;
    }
}

// proj2: xz2 = seq @ W2 + b2  ([50000,256]x[256,1024]); 2 cols x 16 rows/thread
__global__ __launch_bounds__(256, 1) void proj2(const float* __restrict__ W2,
                                                const float* __restrict__ b2) {
    extern __shared__ float sm[];
    float* ws = sm;                 // [64][256] rotation-swizzled W strip
    float* At = sm + 64 * 256;      // [128][256] row-major A tile
    const int tid = threadIdx.x;
    const int nbase = blockIdx.x * 64;
    const int mbase = blockIdx.y * P2M;
    const int M = Tsz * Bsz;

    #pragma unroll
    for (int bb = 0; bb < 8; ++bb) {
        float tf[8];
        #pragma unroll
        for (int i = 0; i < 8; ++i) {
            int idx = tid + (bb * 8 + i) * 256;
            int k = idx >> 6, c = idx & 63;
            tf[i] = __ldg(W2 + k * G4 + nbase + c);
        }
        #pragma unroll
        for (int i = 0; i < 8; ++i) {
            int idx = tid + (bb * 8 + i) * 256;
            int k = idx >> 6, c = idx & 63;
            ws[c * 256 + ((((k >> 2) + c) & 63) << 2) + (k & 3)] = tf[i];
        }
    }
    {
        const float4* sq4 = (const float4*)g_seq;
        float4* At4 = (float4*)At;
        #pragma unroll
        for (int bb = 0; bb < 4; ++bb) {
            float4 tf[8];
            #pragma unroll
            for (int i = 0; i < 8; ++i) {
                int idx = tid + (bb * 8 + i) * 256;
                int r = idx >> 6, k4 = idx & 63;
                int m = mbase + r;
                tf[i] = (m < M) ? __ldg(sq4 + (size_t)m * 64 + k4)
                                : make_float4(0.f, 0.f, 0.f, 0.f);
            }
            #pragma unroll
            for (int i = 0; i < 8; ++i)
                At4[tid + (bb * 8 + i) * 256] = tf[i];
        }
    }
    __syncthreads();

    const int tx = tid & 31;              // cols tx, tx+32
    const int ty = tid >> 5;              // 8 row-groups x 16 rows
    const int r0 = ty * 16;
    const float* w0 = ws + tx * 256;
    const float* w1p = ws + (tx + 32) * 256;
    const float* al  = At + r0 * 256;

    unsigned long long a0[16], a1[16];
    #pragma unroll
    for (int i = 0; i < 16; ++i) { a0[i] = 0ull; a1[i] = 0ull; }

    #pragma unroll 2
    for (int k = 0; k < 256; k += 4) {
        int i4 = k >> 2;
        ulonglong2 uva = *reinterpret_cast<const ulonglong2*>(w0  + (((tx + i4) & 63) << 2));
        ulonglong2 uvb = *reinterpret_cast<const ulonglong2*>(w1p + (((tx + 32 + i4) & 63) << 2));
        #pragma unroll
        for (int i = 0; i < 16; ++i) {
            ulonglong2 hv = *reinterpret_cast<const ulonglong2*>(al + i * 256 + k);
            ffma2(a0[i], hv.x, uva.x); ffma2(a0[i], hv.y, uva.y);
            ffma2(a1[i], hv.x, uvb.x); ffma2(a1[i], hv.y, uvb.y);
        }
    }
    float bbA = b2[nbase + tx];
    float bbB = b2[nbase + tx + 32];
    #pragma unroll
    for (int i = 0; i < 16; ++i) {
        int m = mbase + r0 + i;
        if (m < M) {
            float lo, hi;
            unpack2(a0[i], lo, hi);
            g_xz2[(size_t)m * G4 + nbase + tx] = lo + hi + bbA;
            unpack2(a1[i], lo, hi);
            g_xz2[(size_t)m * G4 + nbase + tx + 32] = lo + hi + bbB;
        }
    }
}

__global__ __launch_bounds__(256) void head(const float* __restrict__ Wd,
                                            const float* __restrict__ bd,
                                            const float* __restrict__ Ws,
                                            const float* __restrict__ bs,
                                            float* __restrict__ out) {
    __shared__ float hrow[Hsz];
    __shared__ float hid[Dsz];
    __shared__ float lbuf[Csz];
    __shared__ float ebuf[Csz];
    int b = blockIdx.x, tid = threadIdx.x;
    hrow[tid] = g_h2a[b * Hsz + tid];   // t=249 odd -> buffer 'a'
    __syncthreads();
    if (tid < Dsz) {
        float s = bd[tid];
        #pragma unroll 8
        for (int k = 0; k < Hsz; ++k) s += hrow[k] * Wd[k * Dsz + tid];
        hid[tid] = fmaxf(s, 0.f);
    }
    __syncthreads();
    if (tid < Csz) {
        float s = bs[tid];
        for (int d = 0; d < Dsz; ++d) s += hid[d] * Ws[d * Csz + tid];
        lbuf[tid] = s;
    }
    __syncthreads();
    if (tid < Csz) {
        float m = lbuf[0];
        #pragma unroll
        for (int j = 1; j < Csz; ++j) m = fmaxf(m, lbuf[j]);
        ebuf[tid] = __expf(lbuf[tid] - m);
    }
    __syncthreads();
    if (tid < Csz) {
        float sum = 0.f;
        #pragma unroll
        for (int j = 0; j < Csz; ++j) sum += ebuf[j];
        out[b * Csz + tid] = ebuf[tid] / sum;
    }
}

extern "C" void kernel_launch(void* const* d_in, const int* in_sizes, int n_in,
                              void* d_out, int out_size) {
    (void)in_sizes; (void)n_in; (void)out_size;
    const float* inputs = (const float*)d_in[0];
    const float* W1 = (const float*)d_in[1];
    const float* U1 = (const float*)d_in[2];
    const float* b1 = (const float*)d_in[3];
    const float* W2 = (const float*)d_in[4];
    const float* U2 = (const float*)d_in[5];
    const float* b2 = (const float*)d_in[6];
    const float* Wd = (const float*)d_in[7];
    const float* bd = (const float*)d_in[8];
    const float* Ws = (const float*)d_in[9];
    const float* bs = (const float*)d_in[10];
    float* out = (float*)d_out;

    // pad lstm smem so only 1 CTA/SM fits (guarantees 144-CTA co-residency)
    const int SM_STEP = 124 * 1024;
    const int SM_PROJ = (64 * 256 + P2M * 256) * 4;   // 192KB
    cudaFuncSetAttribute(lstm_layer, cudaFuncAttributeMaxDynamicSharedMemorySize, SM_STEP);
    cudaFuncSetAttribute(proj2,      cudaFuncAttributeMaxDynamicSharedMemorySize, SM_PROJ);

    zero_state<<<(2 * NROWT * Tsz + 255) / 256, 256>>>();

    dim3 lg(NCOLT, NROWT);
    lstm_layer<<<lg, NTHR, SM_STEP>>>(0, U1, W1, b1, inputs);
    proj2<<<dim3(16, (Tsz * Bsz + P2M - 1) / P2M), 256, SM_PROJ>>>(W2, b2);
    lstm_layer<<<lg, NTHR, SM_STEP>>>(1, U2, W1, b1, inputs);
    head<<<Bsz, 256>>>(Wd, bd, Ws, bs, out);
}

// round 15
// speedup vs baseline: 1.3960x; 1.3960x over previous
#include <cuda_runtime.h>

#define Bsz 200
#define Tsz 250
#define Fsz 14
#define Hsz 256
#define G4  1024
#define Dsz 164
#define Csz 8
#define NCOLT 16
#define NROWT 9
#define RPT   24
#define ZS_LD 25
#define P2M   128
#define ARRIVALS (16u * NCOLT)   // 16 warps per CTA x 16 CTAs per row group

__device__ float g_xz2[Tsz * Bsz * G4];
__device__ float g_seq[Tsz * Bsz * Hsz];
__device__ float g_h1a[Bsz * Hsz];
__device__ float g_h1b[Bsz * Hsz];
__device__ float g_h2a[Bsz * Hsz];
__device__ float g_h2b[Bsz * Hsz];
__device__ unsigned g_scnt[2][NROWT][Tsz];   // per-step warp-arrival counters

__device__ __forceinline__ void ffma2(unsigned long long& d, unsigned long long a, unsigned long long b) {
    asm("fma.rn.f32x2 %0, %1, %2, %0;" : "+l"(d) : "l"(a), "l"(b));
}
__device__ __forceinline__ void unpack2(unsigned long long v, float& lo, float& hi) {
    unsigned int l, h;
    asm("mov.b64 {%0, %1}, %2;" : "=r"(l), "=r"(h) : "l"(v));
    lo = __uint_as_float(l); hi = __uint_as_float(h);
}
__device__ __forceinline__ unsigned ld_acquire(const unsigned* p) {
    unsigned v;
    asm volatile("ld.acquire.gpu.u32 %0, [%1];" : "=r"(v) : "l"(p) : "memory");
    return v;
}
// ACCURATE activations — the recurrence compounds error over 250 steps.
// Fast __expf tanh measured at rel_err 1.2e-3 (FAIL); these give 6.9e-8.
__device__ __forceinline__ float sigmoidf_(float x) {
    return 1.0f / (1.0f + __expf(-x));
}
__device__ __forceinline__ float tanh_acc(float x) { return tanhf(x); }

__global__ void zero_state() {
    int i = blockIdx.x * blockDim.x + threadIdx.x;
    if (i < 2 * NROWT * Tsz) ((unsigned*)g_scnt)[i] = 0u;
}

// persistent LSTM layer: grid (16,9)=144 CTAs, 512 thr, all 250 steps inside.
// CTA tile 24 rows x 16 h-cols (64 gate cols).
// thread = 2 gate-cols (c, c+32) x 6 rows x k-quarter (R13 layout).
// Release is per-warp (RED.ADD after own gate cells): no block sync at step end.
__global__ __launch_bounds__(512, 1) void lstm_layer(
    int layer, const float* __restrict__ U,
    const float* __restrict__ W1, const float* __restrict__ b1,
    const float* __restrict__ inputs)
{
    extern __shared__ float smem[];
    float* ust = smem;                    // [64][256] U strip, rotation-swizzled
    float* hst = ust + 64 * 256;          // [24][256] h tile, row-major
    float* zs  = hst + RPT * 256;         // [4][64][ZS_LD] partials per k-quarter
    float* w1s = zs + 4 * 64 * ZS_LD;     // [14][64]
    float* b1s = w1s + Fsz * 64;          // [64]
    float* xin = b1s + 64;                // [24][16]
    __shared__ float csh[RPT * 16];       // cell state, CTA-private

    const int tid   = threadIdx.x;
    const int lane  = tid & 31;
    const int jbase = blockIdx.x * 16;
    const int grp   = blockIdx.y;
    const int rbase = grp * RPT;

    float* ha = layer ? g_h2a : g_h1a;
    float* hb = layer ? g_h2b : g_h1b;

    // ---- one-time staging: U strip (rotation swizzle) ----
    #pragma unroll
    for (int bb = 0; bb < 4; ++bb) {
        float tf[8];
        #pragma unroll
        for (int i = 0; i < 8; ++i) {
            int idx = tid + (bb * 8 + i) * 512;
            int k = idx >> 6, c = idx & 63;
            tf[i] = __ldg(U + k * G4 + ((c >> 4) << 8) + jbase + (c & 15));
        }
        #pragma unroll
        for (int i = 0; i < 8; ++i) {
            int idx = tid + (bb * 8 + i) * 512;
            int k = idx >> 6, c = idx & 63;
            ust[c * 256 + ((((k >> 2) + c) & 63) << 2) + (k & 3)] = tf[i];
        }
    }
    if (layer == 0) {
        for (int idx = tid; idx < Fsz * 64; idx += 512) {
            int f = idx >> 6, c = idx & 63;
            w1s[idx] = W1[f * G4 + ((c >> 4) << 8) + jbase + (c & 15)];
        }
        if (tid < 64) b1s[tid] = b1[((tid >> 4) << 8) + jbase + (tid & 15)];
    }
    if (tid < RPT * 16) csh[tid] = 0.f;
    __syncthreads();

    const int c      = tid & 31;          // col-thread: owns cols c and c+32
    const int rowthr = (tid >> 5) & 3;
    const int kg     = tid >> 7;
    const int r0     = rowthr * 6;
    const int kbase  = kg * 64;
    const float* u0 = ust + c * 256;
    const float* u1 = ust + (c + 32) * 256;
    const int o0 = (kbase >> 2) + c;          // rotation bases (mod 64 at use)
    const int o1 = (kbase >> 2) + c + 32;
    const float* hlp = hst + r0 * 256 + kbase;
    float* zq = zs + kg * (64 * ZS_LD);
    const int colA = ((c >> 4) << 8) + jbase + (c & 15);
    const int colB = (((c + 32) >> 4) << 8) + jbase + ((c + 32) & 15);

    // layer-0 xin prefetch mapping (one cell per thread, tid<384)
    const int xr = tid >> 4, xf = tid & 15;

    for (int t = 0; t < Tsz; ++t) {
        const float* hin  = (t & 1) ? hb : ha;
        float*       hout = (t & 1) ? ha : hb;

        // ---- prefetch (regs, independent of h(t)) ----
        float xp = 0.f;
        float xzvA[6], xzvB[6];
        if (layer == 0) {
            if (tid < RPT * 16) {
                int row = rbase + xr;
                if (row < Bsz && xf < Fsz)
                    xp = __ldg(inputs + ((size_t)row * Tsz + t) * Fsz + xf);
            }
        } else if (kg == 0) {
            const float* xzt = g_xz2 + (size_t)t * Bsz * G4;
            #pragma unroll
            for (int i = 0; i < 6; ++i) {
                int row = rbase + r0 + i;
                xzvA[i] = (row < Bsz) ? __ldg(xzt + (size_t)row * G4 + colA) : 0.f;
                xzvB[i] = (row < Bsz) ? __ldg(xzt + (size_t)row * G4 + colB) : 0.f;
            }
        }

        // ---- warp-autonomous wait for step t-1 of this row group ----
        if (t > 0) {
            if (lane == 0) {
                const unsigned* sc = &g_scnt[layer][grp][t - 1];
                while (ld_acquire(sc) != ARRIVALS) { }
            }
            __syncwarp();
        }

        // ---- stage h tile (each warp its strided chunk, after its own poll) ----
        if (t == 0) {
            #pragma unroll
            for (int i = 0; i < 3; ++i)
                ((float4*)hst)[tid + i * 512] = make_float4(0.f, 0.f, 0.f, 0.f);
        } else {
            const float4* hin4 = (const float4*)hin;
            float4 tf[3];
            #pragma unroll
            for (int i = 0; i < 3; ++i) {
                int idx = tid + i * 512;
                int r = idx >> 6, k4 = idx & 63;
                int row = rbase + r;
                tf[i] = (row < Bsz) ? __ldcg(hin4 + (size_t)row * 64 + k4)
                                    : make_float4(0.f, 0.f, 0.f, 0.f);
            }
            #pragma unroll
            for (int i = 0; i < 3; ++i)
                ((float4*)hst)[tid + i * 512] = tf[i];
        }
        if (layer == 0 && tid < RPT * 16) xin[tid] = xp;
        __syncthreads();

        // ---- recurrent GEMM (2 cols x 6 rows, this k-quarter) ----
        unsigned long long A0[6], A1[6];
        #pragma unroll
        for (int i = 0; i < 6; ++i) { A0[i] = 0ull; A1[i] = 0ull; }
        #pragma unroll 4
        for (int k = 0; k < 64; k += 4) {
            int i4 = k >> 2;
            ulonglong2 uva = *reinterpret_cast<const ulonglong2*>(u0 + (((o0 + i4) & 63) << 2));
            ulonglong2 uvb = *reinterpret_cast<const ulonglong2*>(u1 + (((o1 + i4) & 63) << 2));
            #pragma unroll
            for (int i = 0; i < 6; ++i) {
                ulonglong2 hv = *reinterpret_cast<const ulonglong2*>(hlp + i * 256 + k);
                ffma2(A0[i], hv.x, uva.x); ffma2(A0[i], hv.y, uva.y);
                ffma2(A1[i], hv.x, uvb.x); ffma2(A1[i], hv.y, uvb.y);
            }
        }
        float zA[6], zB[6];
        #pragma unroll
        for (int i = 0; i < 6; ++i) {
            float lo, hi;
            unpack2(A0[i], lo, hi); zA[i] = lo + hi;
            unpack2(A1[i], lo, hi); zB[i] = lo + hi;
        }

        // kg=0 folds in the input-path contribution for both cols
        if (kg == 0) {
            if (layer == 0) {
                float wA[Fsz], wB[Fsz];
                #pragma unroll
                for (int f = 0; f < Fsz; ++f) {
                    wA[f] = w1s[f * 64 + c];
                    wB[f] = w1s[f * 64 + c + 32];
                }
                float bA = b1s[c], bB = b1s[c + 32];
                #pragma unroll
                for (int i = 0; i < 6; ++i) {
                    float sA = bA, sB = bB;
                    #pragma unroll
                    for (int f = 0; f < Fsz; ++f) {
                        float xv = xin[(r0 + i) * 16 + f];
                        sA += xv * wA[f];
                        sB += xv * wB[f];
                    }
                    zA[i] += sA;
                    zB[i] += sB;
                }
            } else {
                #pragma unroll
                for (int i = 0; i < 6; ++i) { zA[i] += xzvA[i]; zB[i] += xzvB[i]; }
            }
        }
        #pragma unroll
        for (int i = 0; i < 6; ++i) {
            zq[c * ZS_LD + r0 + i]        = zA[i];
            zq[(c + 32) * ZS_LD + r0 + i] = zB[i];
        }
        __syncthreads();

        // ---- gate combine: 384 cells, 1 per thread; sum 4 k-quarter partials ----
        float hn_keep = 0.f;
        int   gidx_keep = -1;
        if (tid < RPT * 16) {
            int j = tid & 15, r = tid >> 4;
            int row = rbase + r;
            if (row < Bsz) {
                float zg4[4];
                #pragma unroll
                for (int g = 0; g < 4; ++g) {
                    float s = 0.f;
                    #pragma unroll
                    for (int q = 0; q < 4; ++q)
                        s += zs[q * (64 * ZS_LD) + (g * 16 + j) * ZS_LD + r];
                    zg4[g] = s;
                }
                float ig = sigmoidf_(zg4[0]), fg = sigmoidf_(zg4[1]);
                float gv = tanh_acc(zg4[2]), og = sigmoidf_(zg4[3]);
                float cn = fg * csh[tid] + ig * gv;
                csh[tid] = cn;
                float hn = og * tanh_acc(cn);
                int gidx = row * Hsz + jbase + j;
                hout[gidx] = hn;                    // critical store first
                hn_keep = hn; gidx_keep = gidx;
            }
        }

        // ---- per-warp release: no block barrier at step end ----
        __syncwarp();                      // orders this warp's hout stores
        if (lane == 0) {
            __threadfence();
            atomicAdd(&g_scnt[layer][grp][t], 1u);   // result unused -> RED
        }
        if (layer == 0 && gidx_keep >= 0)
            g_seq[(size_t)t * Bsz * Hsz + gidx_keep] = hn_keep;
    }
}

// proj2: xz2 = seq @ W2 + b2  ([50000,256]x[256,1024]); 2 cols x 16 rows/thread
__global__ __launch_bounds__(256, 1) void proj2(const float* __restrict__ W2,
                                                const float* __restrict__ b2) {
    extern __shared__ float sm[];
    float* ws = sm;                 // [64][256] rotation-swizzled W strip
    float* At = sm + 64 * 256;      // [128][256] row-major A tile
    const int tid = threadIdx.x;
    const int nbase = blockIdx.x * 64;
    const int mbase = blockIdx.y * P2M;
    const int M = Tsz * Bsz;

    #pragma unroll
    for (int bb = 0; bb < 8; ++bb) {
        float tf[8];
        #pragma unroll
        for (int i = 0; i < 8; ++i) {
            int idx = tid + (bb * 8 + i) * 256;
            int k = idx >> 6, c = idx & 63;
            tf[i] = __ldg(W2 + k * G4 + nbase + c);
        }
        #pragma unroll
        for (int i = 0; i < 8; ++i) {
            int idx = tid + (bb * 8 + i) * 256;
            int k = idx >> 6, c = idx & 63;
            ws[c * 256 + ((((k >> 2) + c) & 63) << 2) + (k & 3)] = tf[i];
        }
    }
    {
        const float4* sq4 = (const float4*)g_seq;
        float4* At4 = (float4*)At;
        #pragma unroll
        for (int bb = 0; bb < 4; ++bb) {
            float4 tf[8];
            #pragma unroll
            for (int i = 0; i < 8; ++i) {
                int idx = tid + (bb * 8 + i) * 256;
                int r = idx >> 6, k4 = idx & 63;
                int m = mbase + r;
                tf[i] = (m < M) ? __ldg(sq4 + (size_t)m * 64 + k4)
                                : make_float4(0.f, 0.f, 0.f, 0.f);
            }
            #pragma unroll
            for (int i = 0; i < 8; ++i)
                At4[tid + (bb * 8 + i) * 256] = tf[i];
        }
    }
    __syncthreads();

    const int tx = tid & 31;              // cols tx, tx+32
    const int ty = tid >> 5;              // 8 row-groups x 16 rows
    const int r0 = ty * 16;
    const float* w0  = ws + tx * 256;
    const float* w1p = ws + (tx + 32) * 256;
    const float* al  = At + r0 * 256;

    unsigned long long a0[16], a1[16];
    #pragma unroll
    for (int i = 0; i < 16; ++i) { a0[i] = 0ull; a1[i] = 0ull; }

    #pragma unroll 2
    for (int k = 0; k < 256; k += 4) {
        int i4 = k >> 2;
        ulonglong2 uva = *reinterpret_cast<const ulonglong2*>(w0  + (((tx + i4) & 63) << 2));
        ulonglong2 uvb = *reinterpret_cast<const ulonglong2*>(w1p + (((tx + 32 + i4) & 63) << 2));
        #pragma unroll
        for (int i = 0; i < 16; ++i) {
            ulonglong2 hv = *reinterpret_cast<const ulonglong2*>(al + i * 256 + k);
            ffma2(a0[i], hv.x, uva.x); ffma2(a0[i], hv.y, uva.y);
            ffma2(a1[i], hv.x, uvb.x); ffma2(a1[i], hv.y, uvb.y);
        }
    }
    float bbA = b2[nbase + tx];
    float bbB = b2[nbase + tx + 32];
    #pragma unroll
    for (int i = 0; i < 16; ++i) {
        int m = mbase + r0 + i;
        if (m < M) {
            float lo, hi;
            unpack2(a0[i], lo, hi);
            g_xz2[(size_t)m * G4 + nbase + tx] = lo + hi + bbA;
            unpack2(a1[i], lo, hi);
            g_xz2[(size_t)m * G4 + nbase + tx + 32] = lo + hi + bbB;
        }
    }
}

__global__ __launch_bounds__(256) void head(const float* __restrict__ Wd,
                                            const float* __restrict__ bd,
                                            const float* __restrict__ Ws,
                                            const float* __restrict__ bs,
                                            float* __restrict__ out) {
    __shared__ float hrow[Hsz];
    __shared__ float hid[Dsz];
    __shared__ float lbuf[Csz];
    __shared__ float ebuf[Csz];
    int b = blockIdx.x, tid = threadIdx.x;
    hrow[tid] = g_h2a[b * Hsz + tid];   // t=249 odd -> buffer 'a'
    __syncthreads();
    if (tid < Dsz) {
        float s = bd[tid];
        #pragma unroll 8
        for (int k = 0; k < Hsz; ++k) s += hrow[k] * Wd[k * Dsz + tid];
        hid[tid] = fmaxf(s, 0.f);
    }
    __syncthreads();
    if (tid < Csz) {
        float s = bs[tid];
        for (int d = 0; d < Dsz; ++d) s += hid[d] * Ws[d * Csz + tid];
        lbuf[tid] = s;
    }
    __syncthreads();
    if (tid < Csz) {
        float m = lbuf[0];
        #pragma unroll
        for (int j = 1; j < Csz; ++j) m = fmaxf(m, lbuf[j]);
        ebuf[tid] = __expf(lbuf[tid] - m);
    }
    __syncthreads();
    if (tid < Csz) {
        float sum = 0.f;
        #pragma unroll
        for (int j = 0; j < Csz; ++j) sum += ebuf[j];
        out[b * Csz + tid] = ebuf[tid] / sum;
    }
}

extern "C" void kernel_launch(void* const* d_in, const int* in_sizes, int n_in,
                              void* d_out, int out_size) {
    (void)in_sizes; (void)n_in; (void)out_size;
    const float* inputs = (const float*)d_in[0];
    const float* W1 = (const float*)d_in[1];
    const float* U1 = (const float*)d_in[2];
    const float* b1 = (const float*)d_in[3];
    const float* W2 = (const float*)d_in[4];
    const float* U2 = (const float*)d_in[5];
    const float* b2 = (const float*)d_in[6];
    const float* Wd = (const float*)d_in[7];
    const float* bd = (const float*)d_in[8];
    const float* Ws = (const float*)d_in[9];
    const float* bs = (const float*)d_in[10];
    float* out = (float*)d_out;

    // pad lstm smem so only 1 CTA/SM fits (guarantees 144-CTA co-residency)
    const int SM_STEP = 124 * 1024;
    const int SM_PROJ = (64 * 256 + P2M * 256) * 4;   // 192KB
    cudaFuncSetAttribute(lstm_layer, cudaFuncAttributeMaxDynamicSharedMemorySize, SM_STEP);
    cudaFuncSetAttribute(proj2,      cudaFuncAttributeMaxDynamicSharedMemorySize, SM_PROJ);

    zero_state<<<(2 * NROWT * Tsz + 255) / 256, 256>>>();

    dim3 lg(NCOLT, NROWT);
    lstm_layer<<<lg, 512, SM_STEP>>>(0, U1, W1, b1, inputs);
    proj2<<<dim3(16, (Tsz * Bsz + P2M - 1) / P2M), 256, SM_PROJ>>>(W2, b2);
    lstm_layer<<<lg, 512, SM_STEP>>>(1, U2, W1, b1, inputs);
    head<<<Bsz, 256>>>(Wd, bd, Ws, bs, out);
}